// round 8
// baseline (speedup 1.0000x reference)
#include <cuda_runtime.h>
#include <cuda_fp16.h>

#define NN 256
#define SS 64
#define BB 1024
#define UNFOLDS 12
#define FAST_STEPS 10          // steps 0..9 f16x2 tanh; steps 10,11 full fp32
#define TB 8
#define NPAIR (NN / 2)         // 128 i-pairs
#define PPG 64                 // pairs per i-group (2 groups)
#define FBLK2 (PPG / 2)        // 32 fast blocks of 2 pairs (4 i's)

// Scratch (device globals — no allocations allowed). Padded rows for prefetch overrun.
__device__ uint2  g_ab16[(NPAIR + 8) * NN];  // [pair][j] {a2, b2} f16x2 (lo=even i, hi=odd i)
__device__ float4 g_abf [(NPAIR + 8) * NN];  // [pair][j] {a_lo, a_hi, b_lo, b_hi} f32
__device__ float2 g_hwe [(NPAIR + 8) * NN];  // [pair][j] {hwe_lo, hwe_hi} f32 (signed; hw = |hwe|)
__device__ float4 g_sparams[SS * NN];        // sensory {a, b, we, wsp} f32
__device__ float  g_sum_hw[NN];
__device__ float  g_sum_hwe[NN];
__device__ float  g_cmt[NN];
__device__ float  g_gl[NN];
__device__ float  g_gv[NN];

__device__ __forceinline__ float tanh_fast(float x) {
    float t;
    asm("tanh.approx.f32 %0, %1;" : "=f"(t) : "f"(x));
    return t;
}

__device__ __forceinline__ float softplus_f(float x) {
    return log1pf(expf(x));   // inputs are in small safe ranges
}

// One i-pair, one batch row (fast path):
//   arg2 = a2*v2 + b2 (HFMA2) ; t2 = tanh.f16x2 (1 MUFU = 2 tanh)
//   unpack to f32 ; num2 += hwe2*t (FFMA2) ; den2 += |hwe2|*t (FFMA2, abs hoisted)
__device__ __forceinline__ void proc_pair16(unsigned v2, uint2 ab,
                                            unsigned long long we2, unsigned long long wa2,
                                            unsigned long long& num2, unsigned long long& den2) {
    unsigned arg, t;
    asm("fma.rn.f16x2 %0, %1, %2, %3;" : "=r"(arg) : "r"(ab.x), "r"(v2), "r"(ab.y));
    asm("tanh.approx.f16x2 %0, %1;" : "=r"(t) : "r"(arg));
    float tlo, thi;
    asm("{ .reg .b16 l, h;\n\t"
        "  mov.b32 {l, h}, %2;\n\t"
        "  cvt.f32.f16 %0, l;\n\t"
        "  cvt.f32.f16 %1, h; }"
        : "=f"(tlo), "=f"(thi) : "r"(t));
    unsigned long long T;
    asm("mov.b64 %0, {%1, %2};" : "=l"(T) : "f"(tlo), "f"(thi));
    asm("fma.rn.f32x2 %0, %1, %2, %0;" : "+l"(num2) : "l"(we2), "l"(T));
    asm("fma.rn.f32x2 %0, %1, %2, %0;" : "+l"(den2) : "l"(wa2), "l"(T));
}

// ---------------------------------------------------------------------------
// Pack recurrent params per i-pair:
// sigmoid(s*(v-m)) = 0.5*(1 + tanh(0.5*s*v - 0.5*s*m)); hw = 0.5*softplus(w)*mask
// hwe = hw*erev (erev = ±1 -> hw = |hwe|)
// ---------------------------------------------------------------------------
__global__ void k_prep(const float* __restrict__ w, const float* __restrict__ sigma,
                       const float* __restrict__ mu, const float* __restrict__ erev,
                       const float* __restrict__ mask) {
    int p = blockIdx.x, j = threadIdx.x;
    int x0 = (2 * p) * NN + j;
    int x1 = (2 * p + 1) * NN + j;

    float a0 = 0.5f * sigma[x0], a1 = 0.5f * sigma[x1];
    float b0 = -a0 * mu[x0],     b1 = -a1 * mu[x1];
    float hw0 = 0.5f * softplus_f(w[x0]) * mask[x0];
    float hw1 = 0.5f * softplus_f(w[x1]) * mask[x1];

    __half2 A = __floats2half2_rn(a0, a1);
    __half2 Bv = __floats2half2_rn(b0, b1);
    uint2 ab;
    ab.x = *reinterpret_cast<unsigned*>(&A);
    ab.y = *reinterpret_cast<unsigned*>(&Bv);
    g_ab16[p * NN + j] = ab;
    g_abf[p * NN + j]  = make_float4(a0, a1, b0, b1);
    g_hwe[p * NN + j]  = make_float2(hw0 * erev[x0], hw1 * erev[x1]);
}

__global__ void k_sprep(const float* __restrict__ sw, const float* __restrict__ ssig,
                        const float* __restrict__ smu, const float* __restrict__ serev,
                        const float* __restrict__ smask) {
    int s = blockIdx.x, j = threadIdx.x;
    int idx = s * NN + j;
    float wsp = softplus_f(sw[idx]) * smask[idx];
    float a   = 0.5f * ssig[idx];
    g_sparams[idx] = make_float4(a, -a * smu[idx], wsp * serev[idx], wsp);
}

__global__ void k_colsums(const float* __restrict__ gleak, const float* __restrict__ vleak,
                          const float* __restrict__ cm) {
    int j = threadIdx.x;
    float shw = 0.f, shwe = 0.f;
    #pragma unroll 8
    for (int p = 0; p < NPAIR; p++) {
        float2 e = g_hwe[p * NN + j];
        shwe += e.x + e.y;
        shw  += fabsf(e.x) + fabsf(e.y);
    }
    g_sum_hw[j]  = shw;
    g_sum_hwe[j] = shwe;
    float gl = softplus_f(gleak[j]);
    g_gl[j]  = gl;
    g_gv[j]  = gl * vleak[j];
    g_cmt[j] = softplus_f(cm[j]) * (float)UNFOLDS;   // softplus(cm) / (1/12)
}

// ---------------------------------------------------------------------------
// Main: 1024 threads = 4 groups of 256 j-threads:
//   gid = tid>>8; bg = gid>>1 (batch half), ig = gid&1 (i half).
// Group (bg,ig): accumulates over pre-neurons i in [ig*128, ig*128+128)
// for batches [bg*4, bg*4+4). Partials merged via SMEM; group owns the
// state update for batches bg*4 + ig*2 + {0,1}.
// Steps 0..9: f16x2 tanh; steps 10,11: full fp32 (accuracy restore).
// ---------------------------------------------------------------------------
__global__ void __launch_bounds__(1024, 1) k_main(const float* __restrict__ inputs,
                                                  const float* __restrict__ state,
                                                  float* __restrict__ out) {
    __shared__ float  v_f[TB][NN];       // canonical fp32 state
    __shared__ __half v_h[TB][NN];       // rounded copy for HFMA2 args
    __shared__ float2 part[TB][NN];      // cross-i-group partial {num, den}
    __shared__ float  xin[TB][SS];

    int tid = threadIdx.x;
    int gid = tid >> 8;          // 0..3
    int bg  = gid >> 1;          // batch half
    int ig  = gid & 1;           // i half
    int j   = tid & 255;
    int b0  = blockIdx.x * TB;
    int bbase = bg * 4;          // first batch this group computes
    int ob    = bbase + ig * 2;  // first batch this group OWNS (updates)

    // inputs: 8 rows x 64 = 512 floats
    if (tid < TB * SS) xin[tid >> 6][tid & 63] = inputs[b0 * SS + tid];

    // state: 2048 floats, 2 per thread
    #pragma unroll
    for (int k = 0; k < 2; k++) {
        int idx = k * 1024 + tid;
        float v = state[b0 * NN + idx];
        int bb = idx >> 8, jj = idx & 255;
        v_f[bb][jj] = v;
        v_h[bb][jj] = __float2half_rn(v);
    }
    __syncthreads();

    // --- sensory pass (step-invariant) for the 2 owned batches ---
    float ncr[2], dcr[2];
    {
        float sn[2] = {0.f, 0.f}, sd[2] = {0.f, 0.f};
        #pragma unroll 2
        for (int s = 0; s < SS; s++) {
            float4 q = g_sparams[s * NN + j];
            #pragma unroll
            for (int k = 0; k < 2; k++) {
                float t  = tanh_fast(fmaf(q.x, xin[ob + k][s], q.y));
                float sg = fmaf(0.5f, t, 0.5f);
                sn[k] = fmaf(q.z, sg, sn[k]);
                sd[k] = fmaf(q.w, sg, sd[k]);
            }
        }
        float gv = g_gv[j], she = g_sum_hwe[j], gl = g_gl[j], shw = g_sum_hw[j];
        float cmt0 = g_cmt[j];
        #pragma unroll
        for (int k = 0; k < 2; k++) {
            ncr[k] = gv + she + sn[k];
            dcr[k] = cmt0 + gl + shw + sd[k] + 1e-8f;
        }
    }
    float cmt = g_cmt[j];

    const int pbase = ig * PPG;          // this group's first pair
    const int ibase = ig * (NN / 2);     // this group's first pre-neuron
    const uint2*  AB = g_ab16 + pbase * NN + j;
    const unsigned long long* WE = reinterpret_cast<const unsigned long long*>(g_hwe) + pbase * NN + j;
    const float4* ABF = g_abf + pbase * NN + j;
    const float2* WEF = g_hwe + pbase * NN + j;

    for (int step = 0; step < UNFOLDS; step++) {
        float num[4], den[4];

        if (step < FAST_STEPS) {
            // ---------- fast f16x2 path ----------
            unsigned long long num2[4], den2[4];
            #pragma unroll
            for (int b = 0; b < 4; b++) { num2[b] = 0ull; den2[b] = 0ull; }

            uint2 ab[2];
            unsigned long long we[2];
            #pragma unroll
            for (int p = 0; p < 2; p++) { ab[p] = AB[p * NN]; we[p] = WE[p * NN]; }

            #pragma unroll 2
            for (int blk = 0; blk < FBLK2; blk++) {
                uint2 cab0 = ab[0], cab1 = ab[1];
                unsigned long long cwe0 = we[0], cwe1 = we[1], cwa0, cwa1;
                asm("and.b64 %0, %1, 0x7FFFFFFF7FFFFFFF;" : "=l"(cwa0) : "l"(cwe0));
                asm("and.b64 %0, %1, 0x7FFFFFFF7FFFFFFF;" : "=l"(cwa1) : "l"(cwe1));
                // prefetch next block (padded rows absorb the overrun)
                ab[0] = AB[((blk + 1) * 2    ) * NN];
                ab[1] = AB[((blk + 1) * 2 + 1) * NN];
                we[0] = WE[((blk + 1) * 2    ) * NN];
                we[1] = WE[((blk + 1) * 2 + 1) * NN];

                #pragma unroll
                for (int k = 0; k < 4; k++) {
                    // 4 halves (2 pairs) = one broadcast LDS.64
                    uint2 vh = *reinterpret_cast<const uint2*>(&v_h[bbase + k][ibase + blk * 4]);
                    proc_pair16(vh.x, cab0, cwe0, cwa0, num2[k], den2[k]);
                    proc_pair16(vh.y, cab1, cwe1, cwa1, num2[k], den2[k]);
                }
            }
            #pragma unroll
            for (int b = 0; b < 4; b++) {
                float nlo, nhi, dlo, dhi;
                asm("mov.b64 {%0, %1}, %2;" : "=f"(nlo), "=f"(nhi) : "l"(num2[b]));
                asm("mov.b64 {%0, %1}, %2;" : "=f"(dlo), "=f"(dhi) : "l"(den2[b]));
                num[b] = nlo + nhi;
                den[b] = dlo + dhi;
            }
        } else {
            // ---------- accurate fp32 path (last 2 steps) ----------
            #pragma unroll
            for (int b = 0; b < 4; b++) { num[b] = 0.f; den[b] = 0.f; }

            #pragma unroll 2
            for (int sb = 0; sb < PPG / 2; sb++) {       // 2 pairs (4 i's) per iter
                float4 a0 = ABF[(sb * 2) * NN];
                float4 a1 = ABF[(sb * 2 + 1) * NN];
                float2 w0 = WEF[(sb * 2) * NN];
                float2 w1 = WEF[(sb * 2 + 1) * NN];
                #pragma unroll
                for (int k = 0; k < 4; k++) {
                    float4 v = *reinterpret_cast<const float4*>(&v_f[bbase + k][ibase + sb * 4]);
                    float t0 = tanh_fast(fmaf(a0.x, v.x, a0.z));
                    float t1 = tanh_fast(fmaf(a0.y, v.y, a0.w));
                    float t2 = tanh_fast(fmaf(a1.x, v.z, a1.z));
                    float t3 = tanh_fast(fmaf(a1.y, v.w, a1.w));
                    num[k] = fmaf(w0.x, t0, num[k]); den[k] = fmaf(fabsf(w0.x), t0, den[k]);
                    num[k] = fmaf(w0.y, t1, num[k]); den[k] = fmaf(fabsf(w0.y), t1, den[k]);
                    num[k] = fmaf(w1.x, t2, num[k]); den[k] = fmaf(fabsf(w1.x), t2, den[k]);
                    num[k] = fmaf(w1.y, t3, num[k]); den[k] = fmaf(fabsf(w1.y), t3, den[k]);
                }
            }
        }

        // write partials for the 2 non-owned batches (owned by the other ig)
        {
            int nb = bbase + (1 - ig) * 2;
            part[nb    ][j] = make_float2(num[nb     - bbase], den[nb     - bbase]);
            part[nb + 1][j] = make_float2(num[nb + 1 - bbase], den[nb + 1 - bbase]);
        }
        __syncthreads();

        // owned batches: merge partials, update state
        #pragma unroll
        for (int k = 0; k < 2; k++) {
            int b = ob + k;
            float2 o = part[b][j];
            float n = num[b - bbase] + o.x;
            float d = den[b - bbase] + o.y;
            float vn = (fmaf(cmt, v_f[b][j], ncr[k]) + n) / (d + dcr[k]);
            v_f[b][j] = vn;
            v_h[b][j] = __float2half_rn(vn);
        }
        __syncthreads();
    }

    // owner writes its 2 rows
    #pragma unroll
    for (int k = 0; k < 2; k++)
        out[(b0 + ob + k) * NN + j] = v_f[ob + k][j];
}

extern "C" void kernel_launch(void* const* d_in, const int* in_sizes, int n_in,
                              void* d_out, int out_size) {
    const float* inputs = (const float*)d_in[0];
    const float* state  = (const float*)d_in[1];
    const float* gleak  = (const float*)d_in[2];
    const float* vleak  = (const float*)d_in[3];
    const float* cm     = (const float*)d_in[4];
    const float* w      = (const float*)d_in[5];
    const float* sigma  = (const float*)d_in[6];
    const float* mu     = (const float*)d_in[7];
    const float* erev   = (const float*)d_in[8];
    const float* sw     = (const float*)d_in[9];
    const float* ssig   = (const float*)d_in[10];
    const float* smu    = (const float*)d_in[11];
    const float* serev  = (const float*)d_in[12];
    const float* mask   = (const float*)d_in[13];
    const float* smask  = (const float*)d_in[14];
    float* out = (float*)d_out;

    k_prep   <<<NPAIR, NN>>>(w, sigma, mu, erev, mask);
    k_sprep  <<<SS, NN>>>(sw, ssig, smu, serev, smask);
    k_colsums<<<1,  NN>>>(gleak, vleak, cm);
    k_main   <<<BB / TB, 1024>>>(inputs, state, out);
}

// round 9
// speedup vs baseline: 1.1080x; 1.1080x over previous
#include <cuda_runtime.h>
#include <cuda_fp16.h>

#define NN 256
#define SS 64
#define BB 1024
#define UNFOLDS 12
#define FAST_STEPS 11          // steps 0..10 f16x2 tanh; step 11 full fp32
#define TB 7                   // batches per CTA (147 CTAs cover 1024 with clamp)
#define GRID 147
#define NPAIR 128              // i-pairs total
#define NQUAD 64               // i-quads total (4 i's each)
#define QPG 32                 // quads per i-group (2 groups)
#define FBLK 16                // fast blocks of 2 quads (8 i's) per group

// Scratch (device globals — no allocations allowed). Padded rows for prefetch overrun.
__device__ uint4  g_abq[(NQUAD + 8) * NN];  // [quad][j] {a2_p0, b2_p0, a2_p1, b2_p1} f16x2
__device__ float4 g_weq[(NQUAD + 8) * NN];  // [quad][j] {hwe_i0, hwe_i1, hwe_i2, hwe_i3} f32
__device__ float4 g_abf[(NPAIR + 8) * NN];  // [pair][j] {a_lo, a_hi, b_lo, b_hi} f32
__device__ float4 g_sparams[SS * NN];       // sensory {a, b, we, wsp} f32
__device__ float  g_sum_hw[NN];
__device__ float  g_sum_hwe[NN];
__device__ float  g_cmt[NN];
__device__ float  g_gl[NN];
__device__ float  g_gv[NN];

__device__ __forceinline__ float tanh_fast(float x) {
    float t;
    asm("tanh.approx.f32 %0, %1;" : "=f"(t) : "f"(x));
    return t;
}

__device__ __forceinline__ float softplus_f(float x) {
    return log1pf(expf(x));
}

// One i-pair, one batch row (fast path):
//   arg2 = a2*v2 + b2 (HFMA2) ; t2 = tanh.f16x2 (1 MUFU = 2 tanh)
//   unpack to f32 ; num2 += hwe2*t (FFMA2) ; den2 += |hwe2|*t (FFMA2, abs hoisted)
__device__ __forceinline__ void proc_pair16(unsigned v2, unsigned a2, unsigned b2,
                                            unsigned long long we2, unsigned long long wa2,
                                            unsigned long long& num2, unsigned long long& den2) {
    unsigned arg, t;
    asm("fma.rn.f16x2 %0, %1, %2, %3;" : "=r"(arg) : "r"(a2), "r"(v2), "r"(b2));
    asm("tanh.approx.f16x2 %0, %1;" : "=r"(t) : "r"(arg));
    float tlo, thi;
    asm("{ .reg .b16 l, h;\n\t"
        "  mov.b32 {l, h}, %2;\n\t"
        "  cvt.f32.f16 %0, l;\n\t"
        "  cvt.f32.f16 %1, h; }"
        : "=f"(tlo), "=f"(thi) : "r"(t));
    unsigned long long T;
    asm("mov.b64 %0, {%1, %2};" : "=l"(T) : "f"(tlo), "f"(thi));
    asm("fma.rn.f32x2 %0, %1, %2, %0;" : "+l"(num2) : "l"(we2), "l"(T));
    asm("fma.rn.f32x2 %0, %1, %2, %0;" : "+l"(den2) : "l"(wa2), "l"(T));
}

// ---------------------------------------------------------------------------
// Pack recurrent params per i-quad (i = 4q..4q+3):
// sigmoid(s*(v-m)) = 0.5*(1 + tanh(0.5*s*v - 0.5*s*m)); hw = 0.5*softplus(w)*mask
// hwe = hw*erev (erev = ±1 -> hw = |hwe|)
// ---------------------------------------------------------------------------
__global__ void k_prep(const float* __restrict__ w, const float* __restrict__ sigma,
                       const float* __restrict__ mu, const float* __restrict__ erev,
                       const float* __restrict__ mask) {
    int q = blockIdx.x, j = threadIdx.x;
    float a[4], b[4], e[4];
    #pragma unroll
    for (int k = 0; k < 4; k++) {
        int x = (4 * q + k) * NN + j;
        a[k] = 0.5f * sigma[x];
        b[k] = -a[k] * mu[x];
        e[k] = 0.5f * softplus_f(w[x]) * mask[x] * erev[x];
    }
    __half2 A0 = __floats2half2_rn(a[0], a[1]);
    __half2 B0 = __floats2half2_rn(b[0], b[1]);
    __half2 A1 = __floats2half2_rn(a[2], a[3]);
    __half2 B1 = __floats2half2_rn(b[2], b[3]);
    uint4 abq;
    abq.x = *reinterpret_cast<unsigned*>(&A0);
    abq.y = *reinterpret_cast<unsigned*>(&B0);
    abq.z = *reinterpret_cast<unsigned*>(&A1);
    abq.w = *reinterpret_cast<unsigned*>(&B1);
    g_abq[q * NN + j] = abq;
    g_weq[q * NN + j] = make_float4(e[0], e[1], e[2], e[3]);
    g_abf[(2 * q)     * NN + j] = make_float4(a[0], a[1], b[0], b[1]);
    g_abf[(2 * q + 1) * NN + j] = make_float4(a[2], a[3], b[2], b[3]);
}

__global__ void k_sprep(const float* __restrict__ sw, const float* __restrict__ ssig,
                        const float* __restrict__ smu, const float* __restrict__ serev,
                        const float* __restrict__ smask) {
    int s = blockIdx.x, j = threadIdx.x;
    int idx = s * NN + j;
    float wsp = softplus_f(sw[idx]) * smask[idx];
    float a   = 0.5f * ssig[idx];
    g_sparams[idx] = make_float4(a, -a * smu[idx], wsp * serev[idx], wsp);
}

__global__ void k_colsums(const float* __restrict__ gleak, const float* __restrict__ vleak,
                          const float* __restrict__ cm) {
    int j = threadIdx.x;
    float shw = 0.f, shwe = 0.f;
    #pragma unroll 8
    for (int q = 0; q < NQUAD; q++) {
        float4 e = g_weq[q * NN + j];
        shwe += (e.x + e.y) + (e.z + e.w);
        shw  += (fabsf(e.x) + fabsf(e.y)) + (fabsf(e.z) + fabsf(e.w));
    }
    g_sum_hw[j]  = shw;
    g_sum_hwe[j] = shwe;
    float gl = softplus_f(gleak[j]);
    g_gl[j]  = gl;
    g_gv[j]  = gl * vleak[j];
    g_cmt[j] = softplus_f(cm[j]) * (float)UNFOLDS;
}

// ---------------------------------------------------------------------------
// Main: 147 CTAs x 512 threads. CTA c owns batches [c*7, c*7+7) (last CTA
// clamps loads and guards stores). 2 i-groups of 256 j-threads each:
// group ig accumulates over pre-neurons i in [ig*128, ig*128+128) for ALL 7
// batches; partials merged via SMEM; group 0 owns batches 0-3, group 1 owns 4-6.
// Steps 0..10: f16x2 tanh; step 11: full fp32 (accuracy restore).
// ---------------------------------------------------------------------------
__global__ void __launch_bounds__(512, 1) k_main(const float* __restrict__ inputs,
                                                 const float* __restrict__ state,
                                                 float* __restrict__ out) {
    __shared__ float  v_f[TB][NN];       // canonical fp32 state
    __shared__ __half v_h[TB][NN];       // rounded copy for HFMA2 args
    __shared__ float2 part[TB][NN];      // cross-group partial {num, den}
    __shared__ float  xin[TB][SS];

    int tid = threadIdx.x;
    int ig  = tid >> 8;          // 0 or 1
    int j   = tid & 255;
    int b0  = blockIdx.x * TB;
    int own_base = ig ? 4 : 0;
    int own_cnt  = ig ? 3 : 4;
    int oth_base = ig ? 0 : 4;
    int oth_cnt  = ig ? 4 : 3;

    // inputs: 7 rows x 64 = 448 floats (clamped for the edge CTA)
    if (tid < TB * SS) xin[tid >> 6][tid & 63] = inputs[min(b0 * SS + tid, BB * SS - 1)];

    // state: 1792 floats (clamped)
    for (int idx = tid; idx < TB * NN; idx += 512) {
        float v = state[min(b0 * NN + idx, BB * NN - 1)];
        int bb = idx >> 8, jj = idx & 255;
        v_f[bb][jj] = v;
        v_h[bb][jj] = __float2half_rn(v);
    }
    __syncthreads();

    // --- sensory pass (step-invariant) for owned batches (<=4) ---
    float ncr[4], dcr[4];
    {
        float sn[4] = {0.f, 0.f, 0.f, 0.f}, sd[4] = {0.f, 0.f, 0.f, 0.f};
        #pragma unroll 2
        for (int s = 0; s < SS; s++) {
            float4 q = g_sparams[s * NN + j];
            #pragma unroll
            for (int k = 0; k < 4; k++) {
                int bx = own_base + min(k, own_cnt - 1);   // clamp keeps loop uniform
                float t  = tanh_fast(fmaf(q.x, xin[bx][s], q.y));
                float sg = fmaf(0.5f, t, 0.5f);
                sn[k] = fmaf(q.z, sg, sn[k]);
                sd[k] = fmaf(q.w, sg, sd[k]);
            }
        }
        float gv = g_gv[j], she = g_sum_hwe[j], gl = g_gl[j], shw = g_sum_hw[j];
        float cmt0 = g_cmt[j];
        #pragma unroll
        for (int k = 0; k < 4; k++) {
            ncr[k] = gv + she + sn[k];
            dcr[k] = cmt0 + gl + shw + sd[k] + 1e-8f;
        }
    }
    float cmt = g_cmt[j];

    const int Q0 = ig * QPG;            // first quad of this group
    const int P0 = ig * (NPAIR / 2);    // first pair
    const int ibase = ig * (NN / 2);    // first pre-neuron
    const uint4*  ABQ = g_abq + Q0 * NN + j;
    const float4* WEQ = g_weq + Q0 * NN + j;
    const float4* ABF = g_abf + P0 * NN + j;

    for (int step = 0; step < UNFOLDS; step++) {
        float num[TB], den[TB];

        if (step < FAST_STEPS) {
            // ---------- fast f16x2 path ----------
            unsigned long long num2[TB], den2[TB];
            #pragma unroll
            for (int b = 0; b < TB; b++) { num2[b] = 0ull; den2[b] = 0ull; }

            // prefetch block 0 (2 quads)
            uint4  ab0 = ABQ[0],  ab1 = ABQ[NN];
            float4 wf0 = WEQ[0],  wf1 = WEQ[NN];

            for (int blk = 0; blk < FBLK; blk++) {
                uint4 cab0 = ab0, cab1 = ab1;
                ulonglong2 cwe0 = *reinterpret_cast<ulonglong2*>(&wf0);
                ulonglong2 cwe1 = *reinterpret_cast<ulonglong2*>(&wf1);
                unsigned long long wa0, wa1, wa2, wa3;
                asm("and.b64 %0, %1, 0x7FFFFFFF7FFFFFFF;" : "=l"(wa0) : "l"(cwe0.x));
                asm("and.b64 %0, %1, 0x7FFFFFFF7FFFFFFF;" : "=l"(wa1) : "l"(cwe0.y));
                asm("and.b64 %0, %1, 0x7FFFFFFF7FFFFFFF;" : "=l"(wa2) : "l"(cwe1.x));
                asm("and.b64 %0, %1, 0x7FFFFFFF7FFFFFFF;" : "=l"(wa3) : "l"(cwe1.y));

                // prefetch next block (padded rows absorb the overrun)
                ab0 = ABQ[((blk + 1) * 2    ) * NN];
                ab1 = ABQ[((blk + 1) * 2 + 1) * NN];
                wf0 = WEQ[((blk + 1) * 2    ) * NN];
                wf1 = WEQ[((blk + 1) * 2 + 1) * NN];

                #pragma unroll
                for (int b = 0; b < TB; b++) {
                    // 8 halves (4 pairs) = one broadcast LDS.128
                    uint4 vh = *reinterpret_cast<const uint4*>(&v_h[b][ibase + blk * 8]);
                    proc_pair16(vh.x, cab0.x, cab0.y, cwe0.x, wa0, num2[b], den2[b]);
                    proc_pair16(vh.y, cab0.z, cab0.w, cwe0.y, wa1, num2[b], den2[b]);
                    proc_pair16(vh.z, cab1.x, cab1.y, cwe1.x, wa2, num2[b], den2[b]);
                    proc_pair16(vh.w, cab1.z, cab1.w, cwe1.y, wa3, num2[b], den2[b]);
                }
            }
            #pragma unroll
            for (int b = 0; b < TB; b++) {
                float nlo, nhi, dlo, dhi;
                asm("mov.b64 {%0, %1}, %2;" : "=f"(nlo), "=f"(nhi) : "l"(num2[b]));
                asm("mov.b64 {%0, %1}, %2;" : "=f"(dlo), "=f"(dhi) : "l"(den2[b]));
                num[b] = nlo + nhi;
                den[b] = dlo + dhi;
            }
        } else {
            // ---------- accurate fp32 path (last step) ----------
            #pragma unroll
            for (int b = 0; b < TB; b++) { num[b] = 0.f; den[b] = 0.f; }

            #pragma unroll 2
            for (int q = 0; q < QPG; q++) {            // one quad (4 i) per iter
                float4 a0 = ABF[(q * 2) * NN];
                float4 a1 = ABF[(q * 2 + 1) * NN];
                float4 e  = WEQ[q * NN];
                #pragma unroll
                for (int b = 0; b < TB; b++) {
                    float4 v = *reinterpret_cast<const float4*>(&v_f[b][ibase + q * 4]);
                    float t0 = tanh_fast(fmaf(a0.x, v.x, a0.z));
                    float t1 = tanh_fast(fmaf(a0.y, v.y, a0.w));
                    float t2 = tanh_fast(fmaf(a1.x, v.z, a1.z));
                    float t3 = tanh_fast(fmaf(a1.y, v.w, a1.w));
                    num[b] = fmaf(e.x, t0, num[b]); den[b] = fmaf(fabsf(e.x), t0, den[b]);
                    num[b] = fmaf(e.y, t1, num[b]); den[b] = fmaf(fabsf(e.y), t1, den[b]);
                    num[b] = fmaf(e.z, t2, num[b]); den[b] = fmaf(fabsf(e.z), t2, den[b]);
                    num[b] = fmaf(e.w, t3, num[b]); den[b] = fmaf(fabsf(e.w), t3, den[b]);
                }
            }
        }

        // write partials for batches the OTHER group owns
        #pragma unroll
        for (int k = 0; k < 4; k++)
            if (k < oth_cnt)
                part[oth_base + k][j] = make_float2(num[oth_base + k], den[oth_base + k]);
        __syncthreads();

        // owned batches: merge partials, update state
        #pragma unroll
        for (int k = 0; k < 4; k++) {
            if (k < own_cnt) {
                int b = own_base + k;
                float2 o = part[b][j];
                float n = num[b] + o.x;
                float d = den[b] + o.y;
                float vn = (fmaf(cmt, v_f[b][j], ncr[k]) + n) / (d + dcr[k]);
                v_f[b][j] = vn;
                v_h[b][j] = __float2half_rn(vn);
            }
        }
        __syncthreads();
    }

    // owner writes its rows (guarded for the edge CTA)
    #pragma unroll
    for (int k = 0; k < 4; k++) {
        if (k < own_cnt) {
            int b = own_base + k;
            if (b0 + b < BB) out[(b0 + b) * NN + j] = v_f[b][j];
        }
    }
}

extern "C" void kernel_launch(void* const* d_in, const int* in_sizes, int n_in,
                              void* d_out, int out_size) {
    const float* inputs = (const float*)d_in[0];
    const float* state  = (const float*)d_in[1];
    const float* gleak  = (const float*)d_in[2];
    const float* vleak  = (const float*)d_in[3];
    const float* cm     = (const float*)d_in[4];
    const float* w      = (const float*)d_in[5];
    const float* sigma  = (const float*)d_in[6];
    const float* mu     = (const float*)d_in[7];
    const float* erev   = (const float*)d_in[8];
    const float* sw     = (const float*)d_in[9];
    const float* ssig   = (const float*)d_in[10];
    const float* smu    = (const float*)d_in[11];
    const float* serev  = (const float*)d_in[12];
    const float* mask   = (const float*)d_in[13];
    const float* smask  = (const float*)d_in[14];
    float* out = (float*)d_out;

    k_prep   <<<NQUAD, NN>>>(w, sigma, mu, erev, mask);
    k_sprep  <<<SS, NN>>>(sw, ssig, smu, serev, smask);
    k_colsums<<<1,  NN>>>(gleak, vleak, cm);
    k_main   <<<GRID, 512>>>(inputs, state, out);
}